// round 8
// baseline (speedup 1.0000x reference)
#include <cuda_runtime.h>
#include <math.h>

#define NN 8192
#define FF 512
#define HH 64
#define NB 4096
#define MAXE 512
#define RPB 8                        /* rows per k_final block */
#define C9 1.2340980408667956e-4f   /* expf(-9) */

// ---------------- scratch (static __device__, no allocations) ----------------
__device__ float  g_fts[NN*HH];          // projected features [N,H]
__device__ float  g_f1[NN];
__device__ float2 g_f2e[NN];             // (f2, exp(f2))
__device__ float  g_lo;
__device__ float  g_invw;
__device__ int    g_bstart[NB+1];        // CSR offsets of buckets
__device__ int    g_perm[NN];            // nodes grouped by bucket
__device__ float  g_P0[(NB+1)*HH];       // prefix:  sum_{buckets < b} fts   (P0[NB][h] = S[h])
__device__ float  g_P1[(NB+1)*HH];       // suffix:  sum_{buckets >= b} ef2*fts
__device__ float  g_Db[NB+1];            // suffix:  sum_{buckets >= b} ef2

// ---------------- K1: fts = features @ W (fp32 tiled GEMM) + f1/f2 epilogue ----------------
__global__ __launch_bounds__(256) void k_gemm(const float* __restrict__ A,
                                              const float* __restrict__ Wm,
                                              const float* __restrict__ a1, const float* __restrict__ b1,
                                              const float* __restrict__ a2, const float* __restrict__ b2) {
    __shared__ float As[16][68];   // transposed A tile [k][m], padded
    __shared__ float Bs[16][64];
    const int tid = threadIdx.x;
    const int m0 = blockIdx.x * 64;
    const int ty = tid >> 4, tx = tid & 15;
    const int arow = tid >> 2, akq = (tid & 3) * 4;
    const int brow = tid >> 4, bcol = (tid & 15) * 4;
    float acc[4][4];
#pragma unroll
    for (int i = 0; i < 4; i++)
#pragma unroll
        for (int j = 0; j < 4; j++) acc[i][j] = 0.f;

    for (int k0 = 0; k0 < FF; k0 += 16) {
        float4 av = *(const float4*)&A[(size_t)(m0 + arow) * FF + k0 + akq];
        float4 bv = *(const float4*)&Wm[(size_t)(k0 + brow) * HH + bcol];
        As[akq+0][arow] = av.x; As[akq+1][arow] = av.y;
        As[akq+2][arow] = av.z; As[akq+3][arow] = av.w;
        *(float4*)&Bs[brow][bcol] = bv;
        __syncthreads();
#pragma unroll
        for (int kk = 0; kk < 16; kk++) {
            float4 a4 = *(const float4*)&As[kk][ty * 4];
            float4 b4 = *(const float4*)&Bs[kk][tx * 4];
            float a[4] = {a4.x, a4.y, a4.z, a4.w};
            float b[4] = {b4.x, b4.y, b4.z, b4.w};
#pragma unroll
            for (int i = 0; i < 4; i++)
#pragma unroll
                for (int j = 0; j < 4; j++)
                    acc[i][j] = fmaf(a[i], b[j], acc[i][j]);
        }
        __syncthreads();
    }
#pragma unroll
    for (int i = 0; i < 4; i++) {
        float4 o = make_float4(acc[i][0], acc[i][1], acc[i][2], acc[i][3]);
        *(float4*)&g_fts[(size_t)(m0 + ty * 4 + i) * HH + tx * 4] = o;
    }
    // ---- epilogue: f1/f2/ef2 from register accumulators ----
    float w1[4], w2[4];
#pragma unroll
    for (int j = 0; j < 4; j++) {
        int c = tx * 4 + j;
        w1[j] = __ldg(&a1[c]);
        w2[j] = __ldg(&a2[c]);
    }
    float s1[4], s2[4];
#pragma unroll
    for (int i = 0; i < 4; i++) {
        float t1 = 0.f, t2 = 0.f;
#pragma unroll
        for (int j = 0; j < 4; j++) {
            t1 = fmaf(acc[i][j], w1[j], t1);
            t2 = fmaf(acc[i][j], w2[j], t2);
        }
        s1[i] = t1; s2[i] = t2;
    }
#pragma unroll
    for (int o = 1; o < 16; o <<= 1) {
#pragma unroll
        for (int i = 0; i < 4; i++) {
            s1[i] += __shfl_xor_sync(0xffffffffu, s1[i], o);
            s2[i] += __shfl_xor_sync(0xffffffffu, s2[i], o);
        }
    }
    if (tx == 0) {
        float bb1 = __ldg(&b1[0]), bb2 = __ldg(&b2[0]);
#pragma unroll
        for (int i = 0; i < 4; i++) {
            int r = m0 + ty * 4 + i;
            float f1v = s1[i] + bb1, f2v = s2[i] + bb2;
            g_f1[r] = f1v;
            g_f2e[r] = make_float2(f2v, __expf(f2v));
        }
    }
}

__device__ __forceinline__ int bucket_of(float v, float lo, float invw) {
    float x = (v - lo) * invw;
    int b = (int)x;
    if (b < 0) b = 0;
    if (b > NB - 1) b = NB - 1;
    return b;
}

// ---------------- K2: fused minmax + histogram + scan + scatter (single block, shuffle scans) ----------------
__global__ __launch_bounds__(1024) void k_prep() {
    __shared__ int   hist[NB];      // 16KB, doubles as fill counters after scan
    __shared__ float wred[64];
    __shared__ int   wtot[32];
    __shared__ int   wex[32];
    const int tid = threadIdx.x;
    const int lane = tid & 31, wid = tid >> 5;

    float f2v[8];
    float lo = 3.4e38f, hi = -3.4e38f;
#pragma unroll
    for (int it = 0; it < 8; it++) {
        float v = g_f2e[tid + it * 1024].x;
        f2v[it] = v;
        lo = fminf(lo, v); hi = fmaxf(hi, v);
    }
#pragma unroll
    for (int o = 16; o; o >>= 1) {
        lo = fminf(lo, __shfl_xor_sync(0xffffffffu, lo, o));
        hi = fmaxf(hi, __shfl_xor_sync(0xffffffffu, hi, o));
    }
    if (lane == 0) { wred[wid] = lo; wred[32 + wid] = hi; }
    // zero histogram while reduction settles
    for (int i = tid; i < NB; i += 1024) hist[i] = 0;
    __syncthreads();
    if (tid < 32) {
        float l = wred[tid], h = wred[32 + tid];
#pragma unroll
        for (int o = 16; o; o >>= 1) {
            l = fminf(l, __shfl_xor_sync(0xffffffffu, l, o));
            h = fmaxf(h, __shfl_xor_sync(0xffffffffu, h, o));
        }
        if (tid == 0) {
            float w = h - l;
            wred[0] = l;
            wred[1] = (w > 0.f) ? (float)NB / w : 0.f;
            g_lo = l; g_invw = wred[1];
        }
    }
    __syncthreads();
    const float LO = wred[0], INVW = wred[1];

    int bks[8];
#pragma unroll
    for (int it = 0; it < 8; it++) {
        bks[it] = bucket_of(f2v[it], LO, INVW);
        atomicAdd(&hist[bks[it]], 1);
    }
    __syncthreads();
    // scan: 4 buckets per thread, warp-shuffle hierarchy
    int h4[4];
#pragma unroll
    for (int u = 0; u < 4; u++) h4[u] = hist[tid * 4 + u];
    int tot = h4[0] + h4[1] + h4[2] + h4[3];
    int scan = tot;
#pragma unroll
    for (int o = 1; o < 32; o <<= 1) {
        int t = __shfl_up_sync(0xffffffffu, scan, o);
        if (lane >= o) scan += t;
    }
    if (lane == 31) wtot[wid] = scan;
    __syncthreads();
    if (tid < 32) {
        int v = wtot[tid];
        int s = v;
#pragma unroll
        for (int o = 1; o < 32; o <<= 1) {
            int t = __shfl_up_sync(0xffffffffu, s, o);
            if (tid >= o) s += t;
        }
        wex[tid] = s - v;   // exclusive
    }
    __syncthreads();
    int excl = wex[wid] + (scan - tot);
#pragma unroll
    for (int u = 0; u < 4; u++) {
        int b = tid * 4 + u;
        g_bstart[b] = excl;
        hist[b] = excl;          // becomes fill counter
        excl += h4[u];
    }
    if (tid == 1023) g_bstart[NB] = excl;
    __syncthreads();
    // scatter
#pragma unroll
    for (int it = 0; it < 8; it++) {
        int n = tid + it * 1024;
        int pos = atomicAdd(&hist[bks[it]], 1);
        g_perm[pos] = n;
    }
}

// ---------------- K3: bucket prefix/suffix sums (block per h; block 64 = Db) ----------------
__global__ __launch_bounds__(256) void k_prescan() {
    const int hb = blockIdx.x;              // 0..63 -> h column; 64 -> Db
    const bool isDb = (hb == HH);
    const int tid = threadIdx.x;
    float s0[16], s1[16];
    const int b0 = tid * 16;
    float t0 = 0.f, t1 = 0.f;
#pragma unroll
    for (int u = 0; u < 16; u++) {
        int st = g_bstart[b0 + u], en = g_bstart[b0 + u + 1];
        float a0 = 0.f, a1v = 0.f;
        for (int i = st; i < en; i++) {
            int n = g_perm[i];
            float e = g_f2e[n].y;
            float f = isDb ? 1.f : g_fts[n * HH + hb];
            a0 += f; a1v += e * f;
        }
        s0[u] = a0; s1[u] = a1v; t0 += a0; t1 += a1v;
    }
    __shared__ float sh0[256], sh1[256];
    sh0[tid] = t0; sh1[tid] = t1; __syncthreads();
    for (int off = 1; off < 256; off <<= 1) {   // sh0: forward inclusive; sh1: backward inclusive
        float v0 = (tid >= off) ? sh0[tid - off] : 0.f;
        float v1 = (tid + off < 256) ? sh1[tid + off] : 0.f;
        __syncthreads();
        sh0[tid] += v0; sh1[tid] += v1;
        __syncthreads();
    }
    float run0 = (tid > 0)   ? sh0[tid - 1] : 0.f;
    float run1 = (tid < 255) ? sh1[tid + 1] : 0.f;
    if (!isDb) {
#pragma unroll
        for (int u = 0; u < 16; u++) { g_P0[(b0 + u) * HH + hb] = run0; run0 += s0[u]; }
        if (tid == 255) g_P0[NB * HH + hb] = run0;   // = S[h]
#pragma unroll
        for (int u = 15; u >= 0; u--) { run1 += s1[u]; g_P1[(b0 + u) * HH + hb] = run1; }
        if (tid == 0) g_P1[NB * HH + hb] = 0.f;
    } else {
#pragma unroll
        for (int u = 15; u >= 0; u--) { run1 += s1[u]; g_Db[b0 + u] = run1; }
        if (tid == 0) g_Db[NB] = 0.f;
    }
}

// ---------------- K4: fused bias-stream edge extraction + warp-per-row aggregation ----------------
__global__ __launch_bounds__(256) void k_final(const float* __restrict__ bias,
                                               float* __restrict__ out) {
    const int tid = threadIdx.x;
    const int lane = tid & 31, wid = tid >> 5;
    const int m0 = blockIdx.x * RPB;
    __shared__ int sh_cols[RPB][MAXE];
    __shared__ int sh_cnt[RPB];
    if (tid < RPB) sh_cnt[tid] = 0;
    __syncthreads();

    // ===== Phase 1: stream 8 bias rows, bitmask-compact edge columns into shared =====
    const unsigned lt = (1u << lane) - 1u;
#pragma unroll 1
    for (int r = 0; r < RPB; r++) {
        const float4* brow = (const float4*)(bias + (size_t)(m0 + r) * NN);
        unsigned mask = 0u;
        {
            float4 v[4];
#pragma unroll
            for (int it = 0; it < 4; it++) v[it] = __ldg(&brow[tid + it * 256]);
#pragma unroll
            for (int it = 0; it < 4; it++) {
                mask |= (v[it].x == 0.f ? 1u : 0u) << (it * 4 + 0);
                mask |= (v[it].y == 0.f ? 1u : 0u) << (it * 4 + 1);
                mask |= (v[it].z == 0.f ? 1u : 0u) << (it * 4 + 2);
                mask |= (v[it].w == 0.f ? 1u : 0u) << (it * 4 + 3);
            }
        }
        {
            float4 v[4];
#pragma unroll
            for (int it = 0; it < 4; it++) v[it] = __ldg(&brow[tid + (it + 4) * 256]);
#pragma unroll
            for (int it = 0; it < 4; it++) {
                mask |= (v[it].x == 0.f ? 1u : 0u) << ((it + 4) * 4 + 0);
                mask |= (v[it].y == 0.f ? 1u : 0u) << ((it + 4) * 4 + 1);
                mask |= (v[it].z == 0.f ? 1u : 0u) << ((it + 4) * 4 + 2);
                mask |= (v[it].w == 0.f ? 1u : 0u) << ((it + 4) * 4 + 3);
            }
        }
        int cnt = __popc(mask);
        int scan = cnt;
#pragma unroll
        for (int o = 1; o < 32; o <<= 1) {
            int t = __shfl_up_sync(0xffffffffu, scan, o);
            if (lane >= o) scan += t;
        }
        int wt = __shfl_sync(0xffffffffu, scan, 31);
        int base = 0;
        if (lane == 31) base = atomicAdd(&sh_cnt[r], wt);
        base = __shfl_sync(0xffffffffu, base, 31);
        int pos = base + scan - cnt;
        while (mask) {
            int b = __ffs(mask) - 1;
            mask &= mask - 1;
            if (pos < MAXE) sh_cols[r][pos] = 4 * tid + ((b >> 2) << 10) + (b & 3);
            pos++;
        }
    }
    __syncthreads();

    // ===== Phase 2: warp w owns row m0+w; lane owns h pair (2*lane, 2*lane+1) =====
    const int m = m0 + wid;
    const float f1m = g_f1[m];
    const float ef1 = __expf(f1m);
    int cnt = sh_cnt[wid]; if (cnt > MAXE) cnt = MAXE;

    float Ex = 0.f, Ey = 0.f, Fx = 0.f, Fy = 0.f, Ze = 0.f;
    const int hofs = lane * 2;
    int j = 0;
    for (; j + 4 <= cnt; j += 4) {
        int n0 = sh_cols[wid][j + 0];
        int n1 = sh_cols[wid][j + 1];
        int n2 = sh_cols[wid][j + 2];
        int n3 = sh_cols[wid][j + 3];
        float2 fe0 = g_f2e[n0], fe1 = g_f2e[n1], fe2 = g_f2e[n2], fe3 = g_f2e[n3];
        float2 f0 = *(const float2*)&g_fts[n0 * HH + hofs];
        float2 f1_ = *(const float2*)&g_fts[n1 * HH + hofs];
        float2 f2_ = *(const float2*)&g_fts[n2 * HH + hofs];
        float2 f3 = *(const float2*)&g_fts[n3 * HH + hofs];
        float w0 = (f1m + fe0.x <= 0.f) ? 1.f : ef1 * fe0.y;
        float w1 = (f1m + fe1.x <= 0.f) ? 1.f : ef1 * fe1.y;
        float w2 = (f1m + fe2.x <= 0.f) ? 1.f : ef1 * fe2.y;
        float w3 = (f1m + fe3.x <= 0.f) ? 1.f : ef1 * fe3.y;
        Ex = fmaf(w0, f0.x, Ex); Ey = fmaf(w0, f0.y, Ey); Fx += f0.x; Fy += f0.y;
        Ex = fmaf(w1, f1_.x, Ex); Ey = fmaf(w1, f1_.y, Ey); Fx += f1_.x; Fy += f1_.y;
        Ex = fmaf(w2, f2_.x, Ex); Ey = fmaf(w2, f2_.y, Ey); Fx += f2_.x; Fy += f2_.y;
        Ex = fmaf(w3, f3.x, Ex); Ey = fmaf(w3, f3.y, Ey); Fx += f3.x; Fy += f3.y;
        Ze += w0 + w1 + w2 + w3;
    }
    for (; j < cnt; j++) {
        int n = sh_cols[wid][j];
        float2 fe = g_f2e[n];
        float2 fv = *(const float2*)&g_fts[n * HH + hofs];
        float w = (f1m + fe.x <= 0.f) ? 1.f : ef1 * fe.y;
        Ex = fmaf(w, fv.x, Ex); Ey = fmaf(w, fv.y, Ey);
        Fx += fv.x; Fy += fv.y; Ze += w;
    }

    // ===== Phase 3: dense part via bucket prefix sums (warp-local, lane = h pair) =====
    float t = -f1m;
    float x = (t - g_lo) * g_invw;
    int bq;
    if (x < 0.f) bq = -1;
    else { bq = (int)x; if (bq > NB - 1) bq = NB - 1; }

    float Ax = 0.f, Ay = 0.f, Bx = 0.f, By = 0.f, cntE = 0.f, dE = 0.f;
    if (bq >= 0) {
        int st = g_bstart[bq], en = g_bstart[bq + 1];
        for (int i = st; i < en; i++) {
            int n = g_perm[i];
            float2 fe = g_f2e[n];
            float2 fv = *(const float2*)&g_fts[n * HH + hofs];
            if (fe.x <= t) { Ax += fv.x; Ay += fv.y; cntE += 1.f; }
            else { Bx = fmaf(fe.y, fv.x, Bx); By = fmaf(fe.y, fv.y, By); dE += fe.y; }
        }
    }
    float2 P0v = (bq >= 0) ? *(const float2*)&g_P0[bq * HH + hofs] : make_float2(0.f, 0.f);
    float2 P1v = *(const float2*)&g_P1[(bq + 1) * HH + hofs];
    float  cb  = (bq >= 0) ? (float)g_bstart[bq] : 0.f;
    float  Dbv = g_Db[bq + 1];
    float2 Sh  = *(const float2*)&g_P0[NB * HH + hofs];

    float Dx = (P0v.x + Ax) + ef1 * (P1v.x + Bx);
    float Dy = (P0v.y + Ay) + ef1 * (P1v.y + By);
    float Zd = (cb + cntE) + ef1 * (Dbv + dE);
    float Zs = C9 * Zd + (1.f - C9) * Ze;
    float invZ = 1.f / Zs;
    float vx = (C9 * Dx + (1.f - C9) * Ex) * invZ - 9.f * (Sh.x - Fx);
    float vy = (C9 * Dy + (1.f - C9) * Ey) * invZ - 9.f * (Sh.y - Fy);
    float2 o;
    o.x = (vx > 0.f) ? vx : expm1f(vx);
    o.y = (vy > 0.f) ? vy : expm1f(vy);
    *(float2*)&out[(size_t)m * HH + hofs] = o;
}

// ---------------- launch ----------------
extern "C" void kernel_launch(void* const* d_in, const int* in_sizes, int n_in,
                              void* d_out, int out_size) {
    const float* features = (const float*)d_in[0];
    const float* bias_mat = (const float*)d_in[1];
    const float* Wm       = (const float*)d_in[2];
    const float* a1       = (const float*)d_in[3];
    const float* b1       = (const float*)d_in[4];
    const float* a2       = (const float*)d_in[5];
    const float* b2       = (const float*)d_in[6];
    float* out = (float*)d_out;

    k_gemm   <<<NN / 64, 256>>>(features, Wm, a1, b1, a2, b2);
    k_prep   <<<1, 1024>>>();
    k_prescan<<<HH + 1, 256>>>();
    k_final  <<<NN / RPB, 256>>>(bias_mat, out);
}

// round 9
// speedup vs baseline: 1.1078x; 1.1078x over previous
#include <cuda_runtime.h>
#include <math.h>

#define NN 8192
#define FF 512
#define HH 64
#define NB 4096
#define MAXE 512
#define RPB 4                        /* rows per k_final block */
#define C9 1.2340980408667956e-4f   /* expf(-9) */

// ---------------- scratch (static __device__, no allocations) ----------------
__device__ float  g_fts[NN*HH];          // projected features [N,H]
__device__ float  g_f1[NN];
__device__ float2 g_f2e[NN];             // (f2, exp(f2))
__device__ float  g_lo;
__device__ float  g_invw;
__device__ int    g_bstart[NB+1];        // CSR offsets of buckets
__device__ int    g_perm[NN];            // nodes grouped by bucket (position-sorted)
__device__ float  g_P0[(NB+1)*HH];       // prefix:  sum_{buckets < b} fts   (P0[NB][h] = S[h])
__device__ float  g_P1[(NB+1)*HH];       // suffix:  sum_{buckets >= b} ef2*fts
__device__ float  g_Db[NB+1];            // suffix:  sum_{buckets >= b} ef2

// ---------------- K1: fts = features @ W (fp32 tiled GEMM) + f1/f2 epilogue ----------------
__global__ __launch_bounds__(256) void k_gemm(const float* __restrict__ A,
                                              const float* __restrict__ Wm,
                                              const float* __restrict__ a1, const float* __restrict__ b1,
                                              const float* __restrict__ a2, const float* __restrict__ b2) {
    __shared__ float As[16][68];   // transposed A tile [k][m], padded
    __shared__ float Bs[16][64];
    const int tid = threadIdx.x;
    const int m0 = blockIdx.x * 64;
    const int ty = tid >> 4, tx = tid & 15;
    const int arow = tid >> 2, akq = (tid & 3) * 4;
    const int brow = tid >> 4, bcol = (tid & 15) * 4;
    float acc[4][4];
#pragma unroll
    for (int i = 0; i < 4; i++)
#pragma unroll
        for (int j = 0; j < 4; j++) acc[i][j] = 0.f;

    for (int k0 = 0; k0 < FF; k0 += 16) {
        float4 av = *(const float4*)&A[(size_t)(m0 + arow) * FF + k0 + akq];
        float4 bv = *(const float4*)&Wm[(size_t)(k0 + brow) * HH + bcol];
        As[akq+0][arow] = av.x; As[akq+1][arow] = av.y;
        As[akq+2][arow] = av.z; As[akq+3][arow] = av.w;
        *(float4*)&Bs[brow][bcol] = bv;
        __syncthreads();
#pragma unroll
        for (int kk = 0; kk < 16; kk++) {
            float4 a4 = *(const float4*)&As[kk][ty * 4];
            float4 b4 = *(const float4*)&Bs[kk][tx * 4];
            float a[4] = {a4.x, a4.y, a4.z, a4.w};
            float b[4] = {b4.x, b4.y, b4.z, b4.w};
#pragma unroll
            for (int i = 0; i < 4; i++)
#pragma unroll
                for (int j = 0; j < 4; j++)
                    acc[i][j] = fmaf(a[i], b[j], acc[i][j]);
        }
        __syncthreads();
    }
#pragma unroll
    for (int i = 0; i < 4; i++) {
        float4 o = make_float4(acc[i][0], acc[i][1], acc[i][2], acc[i][3]);
        *(float4*)&g_fts[(size_t)(m0 + ty * 4 + i) * HH + tx * 4] = o;
    }
    // ---- epilogue: f1/f2/ef2 from register accumulators ----
    float w1[4], w2[4];
#pragma unroll
    for (int j = 0; j < 4; j++) {
        int c = tx * 4 + j;
        w1[j] = __ldg(&a1[c]);
        w2[j] = __ldg(&a2[c]);
    }
    float s1[4], s2[4];
#pragma unroll
    for (int i = 0; i < 4; i++) {
        float t1 = 0.f, t2 = 0.f;
#pragma unroll
        for (int j = 0; j < 4; j++) {
            t1 = fmaf(acc[i][j], w1[j], t1);
            t2 = fmaf(acc[i][j], w2[j], t2);
        }
        s1[i] = t1; s2[i] = t2;
    }
#pragma unroll
    for (int o = 1; o < 16; o <<= 1) {
#pragma unroll
        for (int i = 0; i < 4; i++) {
            s1[i] += __shfl_xor_sync(0xffffffffu, s1[i], o);
            s2[i] += __shfl_xor_sync(0xffffffffu, s2[i], o);
        }
    }
    if (tx == 0) {
        float bb1 = __ldg(&b1[0]), bb2 = __ldg(&b2[0]);
#pragma unroll
        for (int i = 0; i < 4; i++) {
            int r = m0 + ty * 4 + i;
            float f1v = s1[i] + bb1, f2v = s2[i] + bb2;
            g_f1[r] = f1v;
            g_f2e[r] = make_float2(f2v, __expf(f2v));
        }
    }
}

__device__ __forceinline__ int bucket_of(float v, float lo, float invw) {
    float x = (v - lo) * invw;
    int b = (int)x;
    if (b < 0) b = 0;
    if (b > NB - 1) b = NB - 1;
    return b;
}

// ---------------- K2: fused minmax + histogram + scan + scatter (single block) ----------------
__global__ __launch_bounds__(1024) void k_prep() {
    __shared__ int   hist[NB];      // 16KB, doubles as fill counters after scan
    __shared__ float wred[64];
    __shared__ int   wtot[32];
    __shared__ int   wex[32];
    const int tid = threadIdx.x;
    const int lane = tid & 31, wid = tid >> 5;

    float f2v[8];
    float lo = 3.4e38f, hi = -3.4e38f;
#pragma unroll
    for (int it = 0; it < 8; it++) {
        float v = g_f2e[tid + it * 1024].x;
        f2v[it] = v;
        lo = fminf(lo, v); hi = fmaxf(hi, v);
    }
#pragma unroll
    for (int o = 16; o; o >>= 1) {
        lo = fminf(lo, __shfl_xor_sync(0xffffffffu, lo, o));
        hi = fmaxf(hi, __shfl_xor_sync(0xffffffffu, hi, o));
    }
    if (lane == 0) { wred[wid] = lo; wred[32 + wid] = hi; }
    for (int i = tid; i < NB; i += 1024) hist[i] = 0;
    __syncthreads();
    if (tid < 32) {
        float l = wred[tid], h = wred[32 + tid];
#pragma unroll
        for (int o = 16; o; o >>= 1) {
            l = fminf(l, __shfl_xor_sync(0xffffffffu, l, o));
            h = fmaxf(h, __shfl_xor_sync(0xffffffffu, h, o));
        }
        if (tid == 0) {
            float w = h - l;
            wred[0] = l;
            wred[1] = (w > 0.f) ? (float)NB / w : 0.f;
            g_lo = l; g_invw = wred[1];
        }
    }
    __syncthreads();
    const float LO = wred[0], INVW = wred[1];

    int bks[8];
#pragma unroll
    for (int it = 0; it < 8; it++) {
        bks[it] = bucket_of(f2v[it], LO, INVW);
        atomicAdd(&hist[bks[it]], 1);
    }
    __syncthreads();
    int h4[4];
#pragma unroll
    for (int u = 0; u < 4; u++) h4[u] = hist[tid * 4 + u];
    int tot = h4[0] + h4[1] + h4[2] + h4[3];
    int scan = tot;
#pragma unroll
    for (int o = 1; o < 32; o <<= 1) {
        int t = __shfl_up_sync(0xffffffffu, scan, o);
        if (lane >= o) scan += t;
    }
    if (lane == 31) wtot[wid] = scan;
    __syncthreads();
    if (tid < 32) {
        int v = wtot[tid];
        int s = v;
#pragma unroll
        for (int o = 1; o < 32; o <<= 1) {
            int t = __shfl_up_sync(0xffffffffu, s, o);
            if (tid >= o) s += t;
        }
        wex[tid] = s - v;   // exclusive
    }
    __syncthreads();
    int excl = wex[wid] + (scan - tot);
#pragma unroll
    for (int u = 0; u < 4; u++) {
        int b = tid * 4 + u;
        g_bstart[b] = excl;
        hist[b] = excl;          // becomes fill counter
        excl += h4[u];
    }
    if (tid == 1023) g_bstart[NB] = excl;
    __syncthreads();
#pragma unroll
    for (int it = 0; it < 8; it++) {
        int n = tid + it * 1024;
        int pos = atomicAdd(&hist[bks[it]], 1);
        g_perm[pos] = n;
    }
}

// ---------------- K3: position-based bucket prefix/suffix (block per h; block 64 = Db) --------
// Thread owns 32 consecutive perm positions (fixed trip count -> fully unrolled, MLP-batched).
// Single ascending walk emits P0 (prefix of fts), P1 (suffix of ef2*fts) and Db at every
// bucket-start position: suffix-at-p = run1 + t1 - local_prefix.
__global__ __launch_bounds__(256) void k_prescan() {
    const int  hb   = blockIdx.x;           // 0..63 -> h column; 64 -> Db
    const bool isDb = (hb == HH);
    const int  tid  = threadIdx.x;
    const int  lane = tid & 31, wrp = tid >> 5;
    const int  p0   = tid * 32;
    const float LO = g_lo, INVW = g_invw;

    int n[32];
#pragma unroll
    for (int u = 0; u < 8; u++) {
        int4 t4 = *(const int4*)&g_perm[p0 + u * 4];
        n[u*4+0] = t4.x; n[u*4+1] = t4.y; n[u*4+2] = t4.z; n[u*4+3] = t4.w;
    }

    // ---- per-thread sums (batched loads, MLP ~16) ----
    float t0 = 0.f, t1 = 0.f;
#pragma unroll
    for (int u = 0; u < 32; u += 8) {
        float e8[8], f8[8];
#pragma unroll
        for (int k = 0; k < 8; k++) {
            int nn = n[u + k];
            float2 fe = g_f2e[nn];
            e8[k] = fe.y;
            f8[k] = isDb ? 1.f : g_fts[nn * HH + hb];
        }
#pragma unroll
        for (int k = 0; k < 8; k++) { t0 += f8[k]; t1 = fmaf(e8[k], f8[k], t1); }
    }

    // ---- block scan: exclusive prefix of t0 (run0), exclusive suffix of t1 (run1) ----
    __shared__ float w0s[8], w1s[8];
    float s0 = t0, s1 = t1;
#pragma unroll
    for (int o = 1; o < 32; o <<= 1) {
        float a = __shfl_up_sync(0xffffffffu, s0, o);
        if (lane >= o) s0 += a;
        float b = __shfl_down_sync(0xffffffffu, s1, o);
        if (lane + o < 32) s1 += b;
    }
    if (lane == 31) w0s[wrp] = s0;
    if (lane == 0)  w1s[wrp] = s1;
    __syncthreads();
    float off0 = 0.f, off1 = 0.f;
#pragma unroll
    for (int i = 0; i < 8; i++) {
        if (i < wrp) off0 += w0s[i];
        if (i > wrp) off1 += w1s[i];
    }
    const float run0 = off0 + (s0 - t0);   // sum of all positions before p0
    const float run1 = off1 + (s1 - t1);   // sum of all positions >= p0+32

    // bucket of position p0-1 (left neighbor)
    int bprev = -1;
    if (tid > 0) {
        int np = g_perm[p0 - 1];
        bprev = bucket_of(g_f2e[np].x, LO, INVW);
    }

    // ---- single ascending walk: emit P0/P1/Db at bucket starts ----
    float runp = run0, acc1 = 0.f;
    int bp = bprev;
#pragma unroll
    for (int u = 0; u < 32; u += 8) {
        float e8[8], f8[8]; int b8[8];
#pragma unroll
        for (int k = 0; k < 8; k++) {
            int nn = n[u + k];
            float2 fe = g_f2e[nn];
            e8[k] = fe.y;
            b8[k] = bucket_of(fe.x, LO, INVW);
            f8[k] = isDb ? 1.f : g_fts[nn * HH + hb];
        }
#pragma unroll
        for (int k = 0; k < 8; k++) {
            int bc = b8[k];
            float Sp = run1 + (t1 - acc1);       // suffix from this position
            for (int q = bp + 1; q <= bc; q++) {
                if (isDb) g_Db[q] = Sp;
                else { g_P0[q * HH + hb] = runp; g_P1[q * HH + hb] = Sp; }
            }
            runp += f8[k];
            acc1 = fmaf(e8[k], f8[k], acc1);
            bp = bc;
        }
    }
    if (tid == 255) {   // tail: empty buckets after last node + sentinel NB
        for (int q = bp + 1; q < NB; q++) {
            if (isDb) g_Db[q] = 0.f;
            else { g_P0[q * HH + hb] = runp; g_P1[q * HH + hb] = 0.f; }
        }
        if (isDb) g_Db[NB] = 0.f;
        else { g_P0[NB * HH + hb] = runp; g_P1[NB * HH + hb] = 0.f; }
    }
}

// ---------------- K4: fused bias-stream edge extraction + warp-per-row aggregation ----------------
__global__ __launch_bounds__(128) void k_final(const float* __restrict__ bias,
                                               float* __restrict__ out) {
    const int tid = threadIdx.x;
    const int lane = tid & 31, wid = tid >> 5;     // 4 warps
    const int m0 = blockIdx.x * RPB;
    __shared__ int sh_cols[RPB][MAXE];             // 8KB
    __shared__ int sh_cnt[RPB];
    if (tid < RPB) sh_cnt[tid] = 0;
    __syncthreads();

    // ===== Phase 1: stream 4 bias rows, 64-bit-mask compaction =====
#pragma unroll 1
    for (int r = 0; r < RPB; r++) {
        const float4* brow = (const float4*)(bias + (size_t)(m0 + r) * NN);
        unsigned long long mask = 0ull;
        {
            float4 v[8];
#pragma unroll
            for (int it = 0; it < 8; it++) v[it] = __ldg(&brow[tid + it * 128]);
#pragma unroll
            for (int it = 0; it < 8; it++) {
                mask |= (v[it].x == 0.f ? 1ull : 0ull) << (it * 4 + 0);
                mask |= (v[it].y == 0.f ? 1ull : 0ull) << (it * 4 + 1);
                mask |= (v[it].z == 0.f ? 1ull : 0ull) << (it * 4 + 2);
                mask |= (v[it].w == 0.f ? 1ull : 0ull) << (it * 4 + 3);
            }
        }
        {
            float4 v[8];
#pragma unroll
            for (int it = 0; it < 8; it++) v[it] = __ldg(&brow[tid + (it + 8) * 128]);
#pragma unroll
            for (int it = 0; it < 8; it++) {
                mask |= (v[it].x == 0.f ? 1ull : 0ull) << ((it + 8) * 4 + 0);
                mask |= (v[it].y == 0.f ? 1ull : 0ull) << ((it + 8) * 4 + 1);
                mask |= (v[it].z == 0.f ? 1ull : 0ull) << ((it + 8) * 4 + 2);
                mask |= (v[it].w == 0.f ? 1ull : 0ull) << ((it + 8) * 4 + 3);
            }
        }
        int cnt = __popcll(mask);
        int scan = cnt;
#pragma unroll
        for (int o = 1; o < 32; o <<= 1) {
            int t = __shfl_up_sync(0xffffffffu, scan, o);
            if (lane >= o) scan += t;
        }
        int wt = __shfl_sync(0xffffffffu, scan, 31);
        int base = 0;
        if (lane == 31) base = atomicAdd(&sh_cnt[r], wt);
        base = __shfl_sync(0xffffffffu, base, 31);
        int pos = base + scan - cnt;
        while (mask) {
            int b = __ffsll((long long)mask) - 1;
            mask &= mask - 1;
            // bit b = it*4+q -> column = 4*tid + it*512 + q
            if (pos < MAXE) sh_cols[r][pos] = 4 * tid + ((b >> 2) << 9) + (b & 3);
            pos++;
        }
    }
    __syncthreads();

    // ===== Phase 2: warp w owns row m0+w; lane owns h pair (2*lane, 2*lane+1) =====
    const int m = m0 + wid;
    const float f1m = g_f1[m];
    const float ef1 = __expf(f1m);
    int cnt = sh_cnt[wid]; if (cnt > MAXE) cnt = MAXE;

    float Ex = 0.f, Ey = 0.f, Fx = 0.f, Fy = 0.f, Ze = 0.f;
    const int hofs = lane * 2;
    int j = 0;
    for (; j + 4 <= cnt; j += 4) {
        int n0 = sh_cols[wid][j + 0];
        int n1 = sh_cols[wid][j + 1];
        int n2 = sh_cols[wid][j + 2];
        int n3 = sh_cols[wid][j + 3];
        float2 fe0 = g_f2e[n0], fe1 = g_f2e[n1], fe2 = g_f2e[n2], fe3 = g_f2e[n3];
        float2 f0 = *(const float2*)&g_fts[n0 * HH + hofs];
        float2 f1_ = *(const float2*)&g_fts[n1 * HH + hofs];
        float2 f2_ = *(const float2*)&g_fts[n2 * HH + hofs];
        float2 f3 = *(const float2*)&g_fts[n3 * HH + hofs];
        float w0 = (f1m + fe0.x <= 0.f) ? 1.f : ef1 * fe0.y;
        float w1 = (f1m + fe1.x <= 0.f) ? 1.f : ef1 * fe1.y;
        float w2 = (f1m + fe2.x <= 0.f) ? 1.f : ef1 * fe2.y;
        float w3 = (f1m + fe3.x <= 0.f) ? 1.f : ef1 * fe3.y;
        Ex = fmaf(w0, f0.x, Ex); Ey = fmaf(w0, f0.y, Ey); Fx += f0.x; Fy += f0.y;
        Ex = fmaf(w1, f1_.x, Ex); Ey = fmaf(w1, f1_.y, Ey); Fx += f1_.x; Fy += f1_.y;
        Ex = fmaf(w2, f2_.x, Ex); Ey = fmaf(w2, f2_.y, Ey); Fx += f2_.x; Fy += f2_.y;
        Ex = fmaf(w3, f3.x, Ex); Ey = fmaf(w3, f3.y, Ey); Fx += f3.x; Fy += f3.y;
        Ze += w0 + w1 + w2 + w3;
    }
    for (; j < cnt; j++) {
        int n = sh_cols[wid][j];
        float2 fe = g_f2e[n];
        float2 fv = *(const float2*)&g_fts[n * HH + hofs];
        float w = (f1m + fe.x <= 0.f) ? 1.f : ef1 * fe.y;
        Ex = fmaf(w, fv.x, Ex); Ey = fmaf(w, fv.y, Ey);
        Fx += fv.x; Fy += fv.y; Ze += w;
    }

    // ===== Phase 3: dense part via bucket prefix sums (warp-local) =====
    float t = -f1m;
    float x = (t - g_lo) * g_invw;
    int bq;
    if (x < 0.f) bq = -1;
    else { bq = (int)x; if (bq > NB - 1) bq = NB - 1; }

    float Ax = 0.f, Ay = 0.f, Bx = 0.f, By = 0.f, cntE = 0.f, dE = 0.f;
    if (bq >= 0) {
        int st = g_bstart[bq], en = g_bstart[bq + 1];
        for (int i = st; i < en; i++) {
            int n = g_perm[i];
            float2 fe = g_f2e[n];
            float2 fv = *(const float2*)&g_fts[n * HH + hofs];
            if (fe.x <= t) { Ax += fv.x; Ay += fv.y; cntE += 1.f; }
            else { Bx = fmaf(fe.y, fv.x, Bx); By = fmaf(fe.y, fv.y, By); dE += fe.y; }
        }
    }
    float2 P0v = (bq >= 0) ? *(const float2*)&g_P0[bq * HH + hofs] : make_float2(0.f, 0.f);
    float2 P1v = *(const float2*)&g_P1[(bq + 1) * HH + hofs];
    float  cb  = (bq >= 0) ? (float)g_bstart[bq] : 0.f;
    float  Dbv = g_Db[bq + 1];
    float2 Sh  = *(const float2*)&g_P0[NB * HH + hofs];

    float Dx = (P0v.x + Ax) + ef1 * (P1v.x + Bx);
    float Dy = (P0v.y + Ay) + ef1 * (P1v.y + By);
    float Zd = (cb + cntE) + ef1 * (Dbv + dE);
    float Zs = C9 * Zd + (1.f - C9) * Ze;
    float invZ = 1.f / Zs;
    float vx = (C9 * Dx + (1.f - C9) * Ex) * invZ - 9.f * (Sh.x - Fx);
    float vy = (C9 * Dy + (1.f - C9) * Ey) * invZ - 9.f * (Sh.y - Fy);
    float2 o;
    o.x = (vx > 0.f) ? vx : expm1f(vx);
    o.y = (vy > 0.f) ? vy : expm1f(vy);
    *(float2*)&out[(size_t)m * HH + hofs] = o;
}

// ---------------- launch ----------------
extern "C" void kernel_launch(void* const* d_in, const int* in_sizes, int n_in,
                              void* d_out, int out_size) {
    const float* features = (const float*)d_in[0];
    const float* bias_mat = (const float*)d_in[1];
    const float* Wm       = (const float*)d_in[2];
    const float* a1       = (const float*)d_in[3];
    const float* b1       = (const float*)d_in[4];
    const float* a2       = (const float*)d_in[5];
    const float* b2       = (const float*)d_in[6];
    float* out = (float*)d_out;

    k_gemm   <<<NN / 64, 256>>>(features, Wm, a1, b1, a2, b2);
    k_prep   <<<1, 1024>>>();
    k_prescan<<<HH + 1, 256>>>();
    k_final  <<<NN / RPB, 128>>>(bias_mat, out);
}

// round 10
// speedup vs baseline: 1.2845x; 1.1595x over previous
#include <cuda_runtime.h>
#include <math.h>

#define NN 8192
#define FF 512
#define HH 64
#define NB 4096
#define MAXE 512
#define C9 1.2340980408667956e-4f   /* expf(-9) */

// ---------------- scratch (static __device__, no allocations) ----------------
__device__ float  g_fts[NN*HH];          // projected features [N,H]
__device__ float  g_f1[NN];
__device__ float2 g_f2e[NN];             // (f2, exp(f2))
__device__ float  g_lo;
__device__ float  g_invw;
__device__ int    g_bstart[NB+1];        // CSR offsets of buckets
__device__ int    g_perm[NN];            // nodes grouped by bucket (position-sorted)
__device__ float  g_P0[(NB+1)*HH];       // prefix:  sum_{buckets < b} fts   (P0[NB][h] = S[h])
__device__ float  g_P1[(NB+1)*HH];       // suffix:  sum_{buckets >= b} ef2*fts
__device__ float  g_Db[NB+1];            // suffix:  sum_{buckets >= b} ef2

// ---------------- K1: fts = features @ W (double-buffered fp32 GEMM) + f1/f2 epilogue --------
__global__ __launch_bounds__(256) void k_gemm(const float* __restrict__ A,
                                              const float* __restrict__ Wm,
                                              const float* __restrict__ a1, const float* __restrict__ b1,
                                              const float* __restrict__ a2, const float* __restrict__ b2) {
    __shared__ float As[16][68];   // transposed A tile [k][m], padded
    __shared__ float Bs[16][64];
    const int tid = threadIdx.x;
    const int m0 = blockIdx.x * 64;
    const int ty = tid >> 4, tx = tid & 15;
    const int arow = tid >> 2, akq = (tid & 3) * 4;
    const int brow = tid >> 4, bcol = (tid & 15) * 4;
    float acc[4][4];
#pragma unroll
    for (int i = 0; i < 4; i++)
#pragma unroll
        for (int j = 0; j < 4; j++) acc[i][j] = 0.f;

    // prefetch first tile
    float4 av = *(const float4*)&A[(size_t)(m0 + arow) * FF + akq];
    float4 bv = *(const float4*)&Wm[(size_t)brow * HH + bcol];

    for (int k0 = 0; k0 < FF; k0 += 16) {
        As[akq+0][arow] = av.x; As[akq+1][arow] = av.y;
        As[akq+2][arow] = av.z; As[akq+3][arow] = av.w;
        *(float4*)&Bs[brow][bcol] = bv;
        __syncthreads();
        if (k0 + 16 < FF) {   // prefetch next tile; latency hides under compute below
            av = *(const float4*)&A[(size_t)(m0 + arow) * FF + (k0 + 16) + akq];
            bv = *(const float4*)&Wm[(size_t)(k0 + 16 + brow) * HH + bcol];
        }
#pragma unroll
        for (int kk = 0; kk < 16; kk++) {
            float4 a4 = *(const float4*)&As[kk][ty * 4];
            float4 b4 = *(const float4*)&Bs[kk][tx * 4];
            float a[4] = {a4.x, a4.y, a4.z, a4.w};
            float b[4] = {b4.x, b4.y, b4.z, b4.w};
#pragma unroll
            for (int i = 0; i < 4; i++)
#pragma unroll
                for (int j = 0; j < 4; j++)
                    acc[i][j] = fmaf(a[i], b[j], acc[i][j]);
        }
        __syncthreads();
    }
#pragma unroll
    for (int i = 0; i < 4; i++) {
        float4 o = make_float4(acc[i][0], acc[i][1], acc[i][2], acc[i][3]);
        *(float4*)&g_fts[(size_t)(m0 + ty * 4 + i) * HH + tx * 4] = o;
    }
    // ---- epilogue: f1/f2/ef2 from register accumulators ----
    float w1[4], w2[4];
#pragma unroll
    for (int j = 0; j < 4; j++) {
        int c = tx * 4 + j;
        w1[j] = __ldg(&a1[c]);
        w2[j] = __ldg(&a2[c]);
    }
    float s1[4], s2[4];
#pragma unroll
    for (int i = 0; i < 4; i++) {
        float t1 = 0.f, t2 = 0.f;
#pragma unroll
        for (int j = 0; j < 4; j++) {
            t1 = fmaf(acc[i][j], w1[j], t1);
            t2 = fmaf(acc[i][j], w2[j], t2);
        }
        s1[i] = t1; s2[i] = t2;
    }
#pragma unroll
    for (int o = 1; o < 16; o <<= 1) {
#pragma unroll
        for (int i = 0; i < 4; i++) {
            s1[i] += __shfl_xor_sync(0xffffffffu, s1[i], o);
            s2[i] += __shfl_xor_sync(0xffffffffu, s2[i], o);
        }
    }
    if (tx == 0) {
        float bb1 = __ldg(&b1[0]), bb2 = __ldg(&b2[0]);
#pragma unroll
        for (int i = 0; i < 4; i++) {
            int r = m0 + ty * 4 + i;
            float f1v = s1[i] + bb1, f2v = s2[i] + bb2;
            g_f1[r] = f1v;
            g_f2e[r] = make_float2(f2v, __expf(f2v));
        }
    }
}

__device__ __forceinline__ int bucket_of(float v, float lo, float invw) {
    float x = (v - lo) * invw;
    int b = (int)x;
    if (b < 0) b = 0;
    if (b > NB - 1) b = NB - 1;
    return b;
}

// ---------------- K2: fused minmax + histogram + scan + scatter (single block) ----------------
__global__ __launch_bounds__(1024) void k_prep() {
    __shared__ int   hist[NB];      // 16KB, doubles as fill counters after scan
    __shared__ float wred[64];
    __shared__ int   wtot[32];
    __shared__ int   wex[32];
    const int tid = threadIdx.x;
    const int lane = tid & 31, wid = tid >> 5;

    float f2v[8];
    float lo = 3.4e38f, hi = -3.4e38f;
#pragma unroll
    for (int it = 0; it < 8; it++) {
        float v = g_f2e[tid + it * 1024].x;
        f2v[it] = v;
        lo = fminf(lo, v); hi = fmaxf(hi, v);
    }
#pragma unroll
    for (int o = 16; o; o >>= 1) {
        lo = fminf(lo, __shfl_xor_sync(0xffffffffu, lo, o));
        hi = fmaxf(hi, __shfl_xor_sync(0xffffffffu, hi, o));
    }
    if (lane == 0) { wred[wid] = lo; wred[32 + wid] = hi; }
    for (int i = tid; i < NB; i += 1024) hist[i] = 0;
    __syncthreads();
    if (tid < 32) {
        float l = wred[tid], h = wred[32 + tid];
#pragma unroll
        for (int o = 16; o; o >>= 1) {
            l = fminf(l, __shfl_xor_sync(0xffffffffu, l, o));
            h = fmaxf(h, __shfl_xor_sync(0xffffffffu, h, o));
        }
        if (tid == 0) {
            float w = h - l;
            wred[0] = l;
            wred[1] = (w > 0.f) ? (float)NB / w : 0.f;
            g_lo = l; g_invw = wred[1];
        }
    }
    __syncthreads();
    const float LO = wred[0], INVW = wred[1];

    int bks[8];
#pragma unroll
    for (int it = 0; it < 8; it++) {
        bks[it] = bucket_of(f2v[it], LO, INVW);
        atomicAdd(&hist[bks[it]], 1);
    }
    __syncthreads();
    int h4[4];
#pragma unroll
    for (int u = 0; u < 4; u++) h4[u] = hist[tid * 4 + u];
    int tot = h4[0] + h4[1] + h4[2] + h4[3];
    int scan = tot;
#pragma unroll
    for (int o = 1; o < 32; o <<= 1) {
        int t = __shfl_up_sync(0xffffffffu, scan, o);
        if (lane >= o) scan += t;
    }
    if (lane == 31) wtot[wid] = scan;
    __syncthreads();
    if (tid < 32) {
        int v = wtot[tid];
        int s = v;
#pragma unroll
        for (int o = 1; o < 32; o <<= 1) {
            int t = __shfl_up_sync(0xffffffffu, s, o);
            if (tid >= o) s += t;
        }
        wex[tid] = s - v;   // exclusive
    }
    __syncthreads();
    int excl = wex[wid] + (scan - tot);
#pragma unroll
    for (int u = 0; u < 4; u++) {
        int b = tid * 4 + u;
        g_bstart[b] = excl;
        hist[b] = excl;          // becomes fill counter
        excl += h4[u];
    }
    if (tid == 1023) g_bstart[NB] = excl;
    __syncthreads();
#pragma unroll
    for (int it = 0; it < 8; it++) {
        int n = tid + it * 1024;
        int pos = atomicAdd(&hist[bks[it]], 1);
        g_perm[pos] = n;
    }
}

// ---------------- K3: single-pass bucket prefix/suffix (512 thr x 16 nodes; block 64 = Db) ----
// All node data held in registers; one ascending walk emits P0/P1/Db at bucket starts.
__global__ __launch_bounds__(512) void k_prescan() {
    const int  hb   = blockIdx.x;           // 0..63 -> h column; 64 -> Db
    const bool isDb = (hb == HH);
    const int  tid  = threadIdx.x;
    const int  lane = tid & 31, wrp = tid >> 5;   // 16 warps
    const int  p0   = tid * 16;
    const float LO = g_lo, INVW = g_invw;

    int n[16];
#pragma unroll
    for (int u = 0; u < 4; u++) {
        int4 t4 = *(const int4*)&g_perm[p0 + u * 4];
        n[u*4+0] = t4.x; n[u*4+1] = t4.y; n[u*4+2] = t4.z; n[u*4+3] = t4.w;
    }
    float e[16], f[16];
    int   b[16];
#pragma unroll
    for (int k = 0; k < 16; k++) {
        float2 fe = g_f2e[n[k]];
        e[k] = fe.y;
        b[k] = bucket_of(fe.x, LO, INVW);
        f[k] = isDb ? 1.f : g_fts[n[k] * HH + hb];
    }
    float t0 = 0.f, t1 = 0.f;
#pragma unroll
    for (int k = 0; k < 16; k++) { t0 += f[k]; t1 = fmaf(e[k], f[k], t1); }

    // ---- block scan: exclusive prefix of t0 (run0), exclusive suffix of t1 (run1) ----
    __shared__ float w0s[16], w1s[16];
    float s0 = t0, s1 = t1;
#pragma unroll
    for (int o = 1; o < 32; o <<= 1) {
        float a = __shfl_up_sync(0xffffffffu, s0, o);
        if (lane >= o) s0 += a;
        float bb = __shfl_down_sync(0xffffffffu, s1, o);
        if (lane + o < 32) s1 += bb;
    }
    if (lane == 31) w0s[wrp] = s0;
    if (lane == 0)  w1s[wrp] = s1;
    __syncthreads();
    float off0 = 0.f, off1 = 0.f;
#pragma unroll
    for (int i = 0; i < 16; i++) {
        if (i < wrp) off0 += w0s[i];
        if (i > wrp) off1 += w1s[i];
    }
    const float run0 = off0 + (s0 - t0);   // sum of all positions before p0
    const float run1 = off1 + (s1 - t1);   // sum of all positions >= p0+16

    int bprev = -1;
    if (tid > 0) {
        int np = g_perm[p0 - 1];
        bprev = bucket_of(g_f2e[np].x, LO, INVW);
    }

    // ---- ascending walk over registers ----
    float runp = run0, acc1 = 0.f;
    int bp = bprev;
#pragma unroll
    for (int k = 0; k < 16; k++) {
        int bc = b[k];
        float Sp = run1 + (t1 - acc1);       // suffix from this position
        for (int q = bp + 1; q <= bc; q++) {
            if (isDb) g_Db[q] = Sp;
            else { g_P0[q * HH + hb] = runp; g_P1[q * HH + hb] = Sp; }
        }
        runp += f[k];
        acc1 = fmaf(e[k], f[k], acc1);
        bp = bc;
    }
    if (tid == 511) {   // tail: empty buckets after last node + sentinel NB
        for (int q = bp + 1; q < NB; q++) {
            if (isDb) g_Db[q] = 0.f;
            else { g_P0[q * HH + hb] = runp; g_P1[q * HH + hb] = 0.f; }
        }
        if (isDb) g_Db[NB] = 0.f;
        else { g_P0[NB * HH + hb] = runp; g_P1[NB * HH + hb] = 0.f; }
    }
}

// ---------------- K4: warp-independent bias-stream + softmax + aggregation ----------------
// 8 warps/block, warp owns one row end-to-end: no block syncs, no shared atomics.
__global__ __launch_bounds__(256) void k_final(const float* __restrict__ bias,
                                               float* __restrict__ out) {
    const int tid = threadIdx.x;
    const int lane = tid & 31, wid = tid >> 5;     // 8 warps
    __shared__ int sh_cols[8][MAXE];               // 16KB
    const int m = blockIdx.x * 8 + wid;

    // ===== Phase 1 (per warp): stream row, bitmask-compact edge columns =====
    const float4* brow = (const float4*)(bias + (size_t)m * NN);
    int base = 0;                                  // warp-uniform running count
#pragma unroll 1
    for (int o = 0; o < 16; o++) {
        float4 v[4];
#pragma unroll
        for (int it = 0; it < 4; it++) v[it] = __ldg(&brow[lane + (o * 4 + it) * 32]);
        unsigned mask = 0u;
#pragma unroll
        for (int it = 0; it < 4; it++) {
            mask |= (v[it].x == 0.f ? 1u : 0u) << (it * 4 + 0);
            mask |= (v[it].y == 0.f ? 1u : 0u) << (it * 4 + 1);
            mask |= (v[it].z == 0.f ? 1u : 0u) << (it * 4 + 2);
            mask |= (v[it].w == 0.f ? 1u : 0u) << (it * 4 + 3);
        }
        int cnt = __popc(mask);
        int scan = cnt;
#pragma unroll
        for (int s = 1; s < 32; s <<= 1) {
            int t = __shfl_up_sync(0xffffffffu, scan, s);
            if (lane >= s) scan += t;
        }
        int wt = __shfl_sync(0xffffffffu, scan, 31);
        int pos = base + scan - cnt;
        base += wt;
        while (mask) {
            int bbit = __ffs(mask) - 1;
            mask &= mask - 1;
            // bit = it*4+q -> float4 index = lane + (o*4+it)*32 -> column = idx*4+q
            int col = ((o * 4 + (bbit >> 2)) * 32 + lane) * 4 + (bbit & 3);
            if (pos < MAXE) sh_cols[wid][pos] = col;
            pos++;
        }
    }
    __syncwarp();
    int cnt = base; if (cnt > MAXE) cnt = MAXE;

    // ===== Phase 2: gather; lane owns h pair (2*lane, 2*lane+1) =====
    const float f1m = g_f1[m];
    const float ef1 = __expf(f1m);
    float Ex = 0.f, Ey = 0.f, Fx = 0.f, Fy = 0.f, Ze = 0.f;
    const int hofs = lane * 2;
    int j = 0;
    for (; j + 4 <= cnt; j += 4) {
        int n0 = sh_cols[wid][j + 0];
        int n1 = sh_cols[wid][j + 1];
        int n2 = sh_cols[wid][j + 2];
        int n3 = sh_cols[wid][j + 3];
        float2 fe0 = g_f2e[n0], fe1 = g_f2e[n1], fe2 = g_f2e[n2], fe3 = g_f2e[n3];
        float2 f0 = *(const float2*)&g_fts[n0 * HH + hofs];
        float2 f1_ = *(const float2*)&g_fts[n1 * HH + hofs];
        float2 f2_ = *(const float2*)&g_fts[n2 * HH + hofs];
        float2 f3 = *(const float2*)&g_fts[n3 * HH + hofs];
        float w0 = (f1m + fe0.x <= 0.f) ? 1.f : ef1 * fe0.y;
        float w1 = (f1m + fe1.x <= 0.f) ? 1.f : ef1 * fe1.y;
        float w2 = (f1m + fe2.x <= 0.f) ? 1.f : ef1 * fe2.y;
        float w3 = (f1m + fe3.x <= 0.f) ? 1.f : ef1 * fe3.y;
        Ex = fmaf(w0, f0.x, Ex); Ey = fmaf(w0, f0.y, Ey); Fx += f0.x; Fy += f0.y;
        Ex = fmaf(w1, f1_.x, Ex); Ey = fmaf(w1, f1_.y, Ey); Fx += f1_.x; Fy += f1_.y;
        Ex = fmaf(w2, f2_.x, Ex); Ey = fmaf(w2, f2_.y, Ey); Fx += f2_.x; Fy += f2_.y;
        Ex = fmaf(w3, f3.x, Ex); Ey = fmaf(w3, f3.y, Ey); Fx += f3.x; Fy += f3.y;
        Ze += w0 + w1 + w2 + w3;
    }
    for (; j < cnt; j++) {
        int n = sh_cols[wid][j];
        float2 fe = g_f2e[n];
        float2 fv = *(const float2*)&g_fts[n * HH + hofs];
        float w = (f1m + fe.x <= 0.f) ? 1.f : ef1 * fe.y;
        Ex = fmaf(w, fv.x, Ex); Ey = fmaf(w, fv.y, Ey);
        Fx += fv.x; Fy += fv.y; Ze += w;
    }

    // ===== Phase 3: dense part via bucket prefix sums (warp-local) =====
    float t = -f1m;
    float x = (t - g_lo) * g_invw;
    int bq;
    if (x < 0.f) bq = -1;
    else { bq = (int)x; if (bq > NB - 1) bq = NB - 1; }

    float Ax = 0.f, Ay = 0.f, Bx = 0.f, By = 0.f, cntE = 0.f, dE = 0.f;
    if (bq >= 0) {
        int st = g_bstart[bq], en = g_bstart[bq + 1];
        for (int i = st; i < en; i++) {
            int n = g_perm[i];
            float2 fe = g_f2e[n];
            float2 fv = *(const float2*)&g_fts[n * HH + hofs];
            if (fe.x <= t) { Ax += fv.x; Ay += fv.y; cntE += 1.f; }
            else { Bx = fmaf(fe.y, fv.x, Bx); By = fmaf(fe.y, fv.y, By); dE += fe.y; }
        }
    }
    float2 P0v = (bq >= 0) ? *(const float2*)&g_P0[bq * HH + hofs] : make_float2(0.f, 0.f);
    float2 P1v = *(const float2*)&g_P1[(bq + 1) * HH + hofs];
    float  cb  = (bq >= 0) ? (float)g_bstart[bq] : 0.f;
    float  Dbv = g_Db[bq + 1];
    float2 Sh  = *(const float2*)&g_P0[NB * HH + hofs];

    float Dx = (P0v.x + Ax) + ef1 * (P1v.x + Bx);
    float Dy = (P0v.y + Ay) + ef1 * (P1v.y + By);
    float Zd = (cb + cntE) + ef1 * (Dbv + dE);
    float Zs = C9 * Zd + (1.f - C9) * Ze;
    float invZ = 1.f / Zs;
    float vx = (C9 * Dx + (1.f - C9) * Ex) * invZ - 9.f * (Sh.x - Fx);
    float vy = (C9 * Dy + (1.f - C9) * Ey) * invZ - 9.f * (Sh.y - Fy);
    float2 o;
    o.x = (vx > 0.f) ? vx : expm1f(vx);
    o.y = (vy > 0.f) ? vy : expm1f(vy);
    *(float2*)&out[(size_t)m * HH + hofs] = o;
}

// ---------------- launch ----------------
extern "C" void kernel_launch(void* const* d_in, const int* in_sizes, int n_in,
                              void* d_out, int out_size) {
    const float* features = (const float*)d_in[0];
    const float* bias_mat = (const float*)d_in[1];
    const float* Wm       = (const float*)d_in[2];
    const float* a1       = (const float*)d_in[3];
    const float* b1       = (const float*)d_in[4];
    const float* a2       = (const float*)d_in[5];
    const float* b2       = (const float*)d_in[6];
    float* out = (float*)d_out;

    k_gemm   <<<NN / 64, 256>>>(features, Wm, a1, b1, a2, b2);
    k_prep   <<<1, 1024>>>();
    k_prescan<<<HH + 1, 512>>>();
    k_final  <<<NN / 8, 256>>>(bias_mat, out);
}

// round 11
// speedup vs baseline: 1.3656x; 1.0632x over previous
#include <cuda_runtime.h>
#include <math.h>

#define NN 8192
#define FF 512
#define HH 64
#define NB 4096
#define MAXE 512
#define GEMM_BLKS (NN / 64)          /* 128 */
#define C9 1.2340980408667956e-4f    /* expf(-9) */

// ---------------- scratch (static __device__, no allocations) ----------------
__device__ float  g_fts[NN*HH];          // projected features [N,H]
__device__ float  g_f1[NN];
__device__ float2 g_f2e[NN];             // (f2, exp(f2))
__device__ float  g_lo;
__device__ float  g_invw;
__device__ int    g_bstart[NB+1];        // CSR offsets of buckets
__device__ int    g_perm[NN];            // nodes grouped by bucket (position-sorted)
__device__ int    g_ecnt[NN];            // edges per row
__device__ int    g_ecols[(size_t)NN*MAXE]; // edge column lists
__device__ float  g_P0[(NB+1)*HH];       // prefix:  sum_{buckets < b} fts   (P0[NB][h] = S[h])
__device__ float  g_P1[(NB+1)*HH];       // suffix:  sum_{buckets >= b} ef2*fts
__device__ float  g_Db[NB+1];            // suffix:  sum_{buckets >= b} ef2

// ---------------- K1: heterogeneous — double-buffered GEMM || lean edge extraction ------------
__global__ __launch_bounds__(256) void k_mega(const float* __restrict__ A,
                                              const float* __restrict__ Wm,
                                              const float* __restrict__ bias,
                                              const float* __restrict__ a1, const float* __restrict__ b1,
                                              const float* __restrict__ a2, const float* __restrict__ b2) {
    const int tid = threadIdx.x;
    if (blockIdx.x < GEMM_BLKS) {
        // ======== GEMM path: fts = features @ W, tile 64x64, double-buffered ========
        __shared__ float As[16][68];
        __shared__ float Bs[16][64];
        const int m0 = blockIdx.x * 64;
        const int ty = tid >> 4, tx = tid & 15;
        const int arow = tid >> 2, akq = (tid & 3) * 4;
        const int brow = tid >> 4, bcol = (tid & 15) * 4;
        float acc[4][4];
#pragma unroll
        for (int i = 0; i < 4; i++)
#pragma unroll
            for (int j = 0; j < 4; j++) acc[i][j] = 0.f;

        float4 av = *(const float4*)&A[(size_t)(m0 + arow) * FF + akq];
        float4 bv = *(const float4*)&Wm[(size_t)brow * HH + bcol];

        for (int k0 = 0; k0 < FF; k0 += 16) {
            As[akq+0][arow] = av.x; As[akq+1][arow] = av.y;
            As[akq+2][arow] = av.z; As[akq+3][arow] = av.w;
            *(float4*)&Bs[brow][bcol] = bv;
            __syncthreads();
            if (k0 + 16 < FF) {   // prefetch next tile under compute
                av = *(const float4*)&A[(size_t)(m0 + arow) * FF + (k0 + 16) + akq];
                bv = *(const float4*)&Wm[(size_t)(k0 + 16 + brow) * HH + bcol];
            }
#pragma unroll
            for (int kk = 0; kk < 16; kk++) {
                float4 a4 = *(const float4*)&As[kk][ty * 4];
                float4 b4 = *(const float4*)&Bs[kk][tx * 4];
                float a[4] = {a4.x, a4.y, a4.z, a4.w};
                float b[4] = {b4.x, b4.y, b4.z, b4.w};
#pragma unroll
                for (int i = 0; i < 4; i++)
#pragma unroll
                    for (int j = 0; j < 4; j++)
                        acc[i][j] = fmaf(a[i], b[j], acc[i][j]);
            }
            __syncthreads();
        }
#pragma unroll
        for (int i = 0; i < 4; i++) {
            float4 o = make_float4(acc[i][0], acc[i][1], acc[i][2], acc[i][3]);
            *(float4*)&g_fts[(size_t)(m0 + ty * 4 + i) * HH + tx * 4] = o;
        }
        // ---- epilogue: f1/f2/ef2 from register accumulators ----
        float w1[4], w2[4];
#pragma unroll
        for (int j = 0; j < 4; j++) {
            int c = tx * 4 + j;
            w1[j] = __ldg(&a1[c]);
            w2[j] = __ldg(&a2[c]);
        }
        float s1[4], s2[4];
#pragma unroll
        for (int i = 0; i < 4; i++) {
            float t1 = 0.f, t2 = 0.f;
#pragma unroll
            for (int j = 0; j < 4; j++) {
                t1 = fmaf(acc[i][j], w1[j], t1);
                t2 = fmaf(acc[i][j], w2[j], t2);
            }
            s1[i] = t1; s2[i] = t2;
        }
#pragma unroll
        for (int o = 1; o < 16; o <<= 1) {
#pragma unroll
            for (int i = 0; i < 4; i++) {
                s1[i] += __shfl_xor_sync(0xffffffffu, s1[i], o);
                s2[i] += __shfl_xor_sync(0xffffffffu, s2[i], o);
            }
        }
        if (tx == 0) {
            float bb1 = __ldg(&b1[0]), bb2 = __ldg(&b2[0]);
#pragma unroll
            for (int i = 0; i < 4; i++) {
                int r = m0 + ty * 4 + i;
                float f1v = s1[i] + bb1, f2v = s2[i] + bb2;
                g_f1[r] = f1v;
                g_f2e[r] = make_float2(f2v, __expf(f2v));
            }
        }
    } else {
        // ======== edge extraction: warp per row, per-edge shared-atomic compaction ========
        const int lane = tid & 31, wid = tid >> 5;
        const int m = (blockIdx.x - GEMM_BLKS) * 8 + wid;
        __shared__ int sh_cols[8][MAXE];
        __shared__ int sh_cnt[8];
        if (lane == 0) sh_cnt[wid] = 0;
        __syncwarp();
        const float4* brow = (const float4*)(bias + (size_t)m * NN);
#pragma unroll 1
        for (int o = 0; o < 8; o++) {
            float4 v[8];
#pragma unroll
            for (int it = 0; it < 8; it++) v[it] = __ldg(&brow[lane + (o * 8 + it) * 32]);  // MLP=8
            unsigned mask = 0u;
#pragma unroll
            for (int it = 0; it < 8; it++) {
                mask |= (v[it].x == 0.f ? 1u : 0u) << (it * 4 + 0);
                mask |= (v[it].y == 0.f ? 1u : 0u) << (it * 4 + 1);
                mask |= (v[it].z == 0.f ? 1u : 0u) << (it * 4 + 2);
                mask |= (v[it].w == 0.f ? 1u : 0u) << (it * 4 + 3);
            }
            while (mask) {                         // avg ~1.3 edges per lane per pass
                int b = __ffs(mask) - 1;
                mask &= mask - 1;
                int pos = atomicAdd(&sh_cnt[wid], 1);
                int col = 4 * lane + o * 1024 + ((b >> 2) << 7) + (b & 3);
                if (pos < MAXE) sh_cols[wid][pos] = col;
            }
        }
        __syncwarp();
        int cnt = sh_cnt[wid]; if (cnt > MAXE) cnt = MAXE;
        for (int j = lane; j < cnt; j += 32) g_ecols[(size_t)m * MAXE + j] = sh_cols[wid][j];
        if (lane == 0) g_ecnt[m] = cnt;
    }
}

__device__ __forceinline__ int bucket_of(float v, float lo, float invw) {
    float x = (v - lo) * invw;
    int b = (int)x;
    if (b < 0) b = 0;
    if (b > NB - 1) b = NB - 1;
    return b;
}

// ---------------- K2: fused minmax + histogram + scan + scatter (single block) ----------------
__global__ __launch_bounds__(1024) void k_prep() {
    __shared__ int   hist[NB];
    __shared__ float wred[64];
    __shared__ int   wtot[32];
    __shared__ int   wex[32];
    const int tid = threadIdx.x;
    const int lane = tid & 31, wid = tid >> 5;

    float f2v[8];
    float lo = 3.4e38f, hi = -3.4e38f;
#pragma unroll
    for (int it = 0; it < 8; it++) {
        float v = g_f2e[tid + it * 1024].x;
        f2v[it] = v;
        lo = fminf(lo, v); hi = fmaxf(hi, v);
    }
#pragma unroll
    for (int o = 16; o; o >>= 1) {
        lo = fminf(lo, __shfl_xor_sync(0xffffffffu, lo, o));
        hi = fmaxf(hi, __shfl_xor_sync(0xffffffffu, hi, o));
    }
    if (lane == 0) { wred[wid] = lo; wred[32 + wid] = hi; }
    for (int i = tid; i < NB; i += 1024) hist[i] = 0;
    __syncthreads();
    if (tid < 32) {
        float l = wred[tid], h = wred[32 + tid];
#pragma unroll
        for (int o = 16; o; o >>= 1) {
            l = fminf(l, __shfl_xor_sync(0xffffffffu, l, o));
            h = fmaxf(h, __shfl_xor_sync(0xffffffffu, h, o));
        }
        if (tid == 0) {
            float w = h - l;
            wred[0] = l;
            wred[1] = (w > 0.f) ? (float)NB / w : 0.f;
            g_lo = l; g_invw = wred[1];
        }
    }
    __syncthreads();
    const float LO = wred[0], INVW = wred[1];

    int bks[8];
#pragma unroll
    for (int it = 0; it < 8; it++) {
        bks[it] = bucket_of(f2v[it], LO, INVW);
        atomicAdd(&hist[bks[it]], 1);
    }
    __syncthreads();
    int h4[4];
#pragma unroll
    for (int u = 0; u < 4; u++) h4[u] = hist[tid * 4 + u];
    int tot = h4[0] + h4[1] + h4[2] + h4[3];
    int scan = tot;
#pragma unroll
    for (int o = 1; o < 32; o <<= 1) {
        int t = __shfl_up_sync(0xffffffffu, scan, o);
        if (lane >= o) scan += t;
    }
    if (lane == 31) wtot[wid] = scan;
    __syncthreads();
    if (tid < 32) {
        int v = wtot[tid];
        int s = v;
#pragma unroll
        for (int o = 1; o < 32; o <<= 1) {
            int t = __shfl_up_sync(0xffffffffu, s, o);
            if (tid >= o) s += t;
        }
        wex[tid] = s - v;
    }
    __syncthreads();
    int excl = wex[wid] + (scan - tot);
#pragma unroll
    for (int u = 0; u < 4; u++) {
        int b = tid * 4 + u;
        g_bstart[b] = excl;
        hist[b] = excl;
        excl += h4[u];
    }
    if (tid == 1023) g_bstart[NB] = excl;
    __syncthreads();
#pragma unroll
    for (int it = 0; it < 8; it++) {
        int n = tid + it * 1024;
        int pos = atomicAdd(&hist[bks[it]], 1);
        g_perm[pos] = n;
    }
}

// ---------------- K3: single-pass bucket prefix/suffix (512 thr x 16 nodes; block 64 = Db) ----
__global__ __launch_bounds__(512) void k_prescan() {
    const int  hb   = blockIdx.x;
    const bool isDb = (hb == HH);
    const int  tid  = threadIdx.x;
    const int  lane = tid & 31, wrp = tid >> 5;
    const int  p0   = tid * 16;
    const float LO = g_lo, INVW = g_invw;

    int n[16];
#pragma unroll
    for (int u = 0; u < 4; u++) {
        int4 t4 = *(const int4*)&g_perm[p0 + u * 4];
        n[u*4+0] = t4.x; n[u*4+1] = t4.y; n[u*4+2] = t4.z; n[u*4+3] = t4.w;
    }
    float e[16], f[16];
    int   b[16];
#pragma unroll
    for (int k = 0; k < 16; k++) {
        float2 fe = g_f2e[n[k]];
        e[k] = fe.y;
        b[k] = bucket_of(fe.x, LO, INVW);
        f[k] = isDb ? 1.f : g_fts[n[k] * HH + hb];
    }
    float t0 = 0.f, t1 = 0.f;
#pragma unroll
    for (int k = 0; k < 16; k++) { t0 += f[k]; t1 = fmaf(e[k], f[k], t1); }

    __shared__ float w0s[16], w1s[16];
    float s0 = t0, s1 = t1;
#pragma unroll
    for (int o = 1; o < 32; o <<= 1) {
        float a = __shfl_up_sync(0xffffffffu, s0, o);
        if (lane >= o) s0 += a;
        float bb = __shfl_down_sync(0xffffffffu, s1, o);
        if (lane + o < 32) s1 += bb;
    }
    if (lane == 31) w0s[wrp] = s0;
    if (lane == 0)  w1s[wrp] = s1;
    __syncthreads();
    float off0 = 0.f, off1 = 0.f;
#pragma unroll
    for (int i = 0; i < 16; i++) {
        if (i < wrp) off0 += w0s[i];
        if (i > wrp) off1 += w1s[i];
    }
    const float run0 = off0 + (s0 - t0);
    const float run1 = off1 + (s1 - t1);

    int bprev = -1;
    if (tid > 0) {
        int np = g_perm[p0 - 1];
        bprev = bucket_of(g_f2e[np].x, LO, INVW);
    }

    float runp = run0, acc1 = 0.f;
    int bp = bprev;
#pragma unroll
    for (int k = 0; k < 16; k++) {
        int bc = b[k];
        float Sp = run1 + (t1 - acc1);
        for (int q = bp + 1; q <= bc; q++) {
            if (isDb) g_Db[q] = Sp;
            else { g_P0[q * HH + hb] = runp; g_P1[q * HH + hb] = Sp; }
        }
        runp += f[k];
        acc1 = fmaf(e[k], f[k], acc1);
        bp = bc;
    }
    if (tid == 511) {
        for (int q = bp + 1; q < NB; q++) {
            if (isDb) g_Db[q] = 0.f;
            else { g_P0[q * HH + hb] = runp; g_P1[q * HH + hb] = 0.f; }
        }
        if (isDb) g_Db[NB] = 0.f;
        else { g_P0[NB * HH + hb] = runp; g_P1[NB * HH + hb] = 0.f; }
    }
}

// ---------------- K4: gather-only softmax + aggregation (warp per row, no bias stream) --------
__global__ __launch_bounds__(256) void k_final(float* __restrict__ out) {
    const int tid = threadIdx.x;
    const int lane = tid & 31, wid = tid >> 5;
    __shared__ int sh_cols[8][MAXE];
    const int m = blockIdx.x * 8 + wid;

    int cnt = g_ecnt[m];
    for (int j = lane; j < cnt; j += 32) sh_cols[wid][j] = __ldg(&g_ecols[(size_t)m * MAXE + j]);
    __syncwarp();

    // ===== edge aggregation: lane owns h pair (2*lane, 2*lane+1) =====
    const float f1m = g_f1[m];
    const float ef1 = __expf(f1m);
    float Ex = 0.f, Ey = 0.f, Fx = 0.f, Fy = 0.f, Ze = 0.f;
    const int hofs = lane * 2;
    int j = 0;
    for (; j + 4 <= cnt; j += 4) {
        int n0 = sh_cols[wid][j + 0];
        int n1 = sh_cols[wid][j + 1];
        int n2 = sh_cols[wid][j + 2];
        int n3 = sh_cols[wid][j + 3];
        float2 fe0 = g_f2e[n0], fe1 = g_f2e[n1], fe2 = g_f2e[n2], fe3 = g_f2e[n3];
        float2 f0 = *(const float2*)&g_fts[n0 * HH + hofs];
        float2 f1_ = *(const float2*)&g_fts[n1 * HH + hofs];
        float2 f2_ = *(const float2*)&g_fts[n2 * HH + hofs];
        float2 f3 = *(const float2*)&g_fts[n3 * HH + hofs];
        float w0 = (f1m + fe0.x <= 0.f) ? 1.f : ef1 * fe0.y;
        float w1 = (f1m + fe1.x <= 0.f) ? 1.f : ef1 * fe1.y;
        float w2 = (f1m + fe2.x <= 0.f) ? 1.f : ef1 * fe2.y;
        float w3 = (f1m + fe3.x <= 0.f) ? 1.f : ef1 * fe3.y;
        Ex = fmaf(w0, f0.x, Ex); Ey = fmaf(w0, f0.y, Ey); Fx += f0.x; Fy += f0.y;
        Ex = fmaf(w1, f1_.x, Ex); Ey = fmaf(w1, f1_.y, Ey); Fx += f1_.x; Fy += f1_.y;
        Ex = fmaf(w2, f2_.x, Ex); Ey = fmaf(w2, f2_.y, Ey); Fx += f2_.x; Fy += f2_.y;
        Ex = fmaf(w3, f3.x, Ex); Ey = fmaf(w3, f3.y, Ey); Fx += f3.x; Fy += f3.y;
        Ze += w0 + w1 + w2 + w3;
    }
    for (; j < cnt; j++) {
        int n = sh_cols[wid][j];
        float2 fe = g_f2e[n];
        float2 fv = *(const float2*)&g_fts[n * HH + hofs];
        float w = (f1m + fe.x <= 0.f) ? 1.f : ef1 * fe.y;
        Ex = fmaf(w, fv.x, Ex); Ey = fmaf(w, fv.y, Ey);
        Fx += fv.x; Fy += fv.y; Ze += w;
    }

    // ===== dense part via bucket prefix sums (warp-local) =====
    float t = -f1m;
    float x = (t - g_lo) * g_invw;
    int bq;
    if (x < 0.f) bq = -1;
    else { bq = (int)x; if (bq > NB - 1) bq = NB - 1; }

    float Ax = 0.f, Ay = 0.f, Bx = 0.f, By = 0.f, cntE = 0.f, dE = 0.f;
    if (bq >= 0) {
        int st = g_bstart[bq], en = g_bstart[bq + 1];
        for (int i = st; i < en; i++) {
            int n = g_perm[i];
            float2 fe = g_f2e[n];
            float2 fv = *(const float2*)&g_fts[n * HH + hofs];
            if (fe.x <= t) { Ax += fv.x; Ay += fv.y; cntE += 1.f; }
            else { Bx = fmaf(fe.y, fv.x, Bx); By = fmaf(fe.y, fv.y, By); dE += fe.y; }
        }
    }
    float2 P0v = (bq >= 0) ? *(const float2*)&g_P0[bq * HH + hofs] : make_float2(0.f, 0.f);
    float2 P1v = *(const float2*)&g_P1[(bq + 1) * HH + hofs];
    float  cb  = (bq >= 0) ? (float)g_bstart[bq] : 0.f;
    float  Dbv = g_Db[bq + 1];
    float2 Sh  = *(const float2*)&g_P0[NB * HH + hofs];

    float Dx = (P0v.x + Ax) + ef1 * (P1v.x + Bx);
    float Dy = (P0v.y + Ay) + ef1 * (P1v.y + By);
    float Zd = (cb + cntE) + ef1 * (Dbv + dE);
    float Zs = C9 * Zd + (1.f - C9) * Ze;
    float invZ = 1.f / Zs;
    float vx = (C9 * Dx + (1.f - C9) * Ex) * invZ - 9.f * (Sh.x - Fx);
    float vy = (C9 * Dy + (1.f - C9) * Ey) * invZ - 9.f * (Sh.y - Fy);
    float2 o;
    o.x = (vx > 0.f) ? vx : expm1f(vx);
    o.y = (vy > 0.f) ? vy : expm1f(vy);
    *(float2*)&out[(size_t)m * HH + hofs] = o;
}

// ---------------- launch ----------------
extern "C" void kernel_launch(void* const* d_in, const int* in_sizes, int n_in,
                              void* d_out, int out_size) {
    const float* features = (const float*)d_in[0];
    const float* bias_mat = (const float*)d_in[1];
    const float* Wm       = (const float*)d_in[2];
    const float* a1       = (const float*)d_in[3];
    const float* b1       = (const float*)d_in[4];
    const float* a2       = (const float*)d_in[5];
    const float* b2       = (const float*)d_in[6];
    float* out = (float*)d_out;

    k_mega   <<<GEMM_BLKS + NN / 8, 256>>>(features, Wm, bias_mat, a1, b1, a2, b2);
    k_prep   <<<1, 1024>>>();
    k_prescan<<<HH + 1, 512>>>();
    k_final  <<<NN / 8, 256>>>(out);
}